// round 1
// baseline (speedup 1.0000x reference)
#include <cuda_runtime.h>

#define BB 64
#define PP 1024
#define TT 1024

// Scratch: 256 MB Gibbs kernel + iterates (static __device__ — allowed).
__device__ float g_K[(size_t)BB * PP * TT];
__device__ float g_u[BB * PP];
__device__ float g_v[BB * TT];

// Kernel 0: K = exp(-C/reg) (float4), also init u = 1.
__global__ void k_exp(const float* __restrict__ C, const float* __restrict__ reg) {
    size_t i4 = (size_t)blockIdx.x * blockDim.x + threadIdx.x;   // float4 index
    float ninv = -1.0f / reg[0];
    float4 c = ((const float4*)C)[i4];
    float4 k;
    k.x = __expf(c.x * ninv);
    k.y = __expf(c.y * ninv);
    k.z = __expf(c.z * ninv);
    k.w = __expf(c.w * ninv);
    ((float4*)g_K)[i4] = k;
    if (i4 < (BB * PP) / 4) {
        ((float4*)g_u)[i4] = make_float4(1.f, 1.f, 1.f, 1.f);
    }
}

// Kernel 1: Ktu[b,t] = sum_p K[b,p,t] * u[b,p];  v = tgt / Ktu   (fused)
// Block = 256 threads over t; grid = (T/256, B). u row staged in shared.
__global__ void k_ktu(const float* __restrict__ tgt) {
    __shared__ float us[PP];
    const int b = blockIdx.y;
    const int t = blockIdx.x * 256 + threadIdx.x;
    for (int p = threadIdx.x; p < PP; p += 256)
        us[p] = g_u[b * PP + p];
    __syncthreads();

    const float* __restrict__ Kb = g_K + (size_t)b * PP * TT + t;
    float a0 = 0.f, a1 = 0.f, a2 = 0.f, a3 = 0.f;
#pragma unroll 4
    for (int p = 0; p < PP; p += 4) {
        a0 += Kb[(size_t)(p + 0) * TT] * us[p + 0];
        a1 += Kb[(size_t)(p + 1) * TT] * us[p + 1];
        a2 += Kb[(size_t)(p + 2) * TT] * us[p + 2];
        a3 += Kb[(size_t)(p + 3) * TT] * us[p + 3];
    }
    const float acc = (a0 + a1) + (a2 + a3);
    const int o = b * TT + t;
    g_v[o] = tgt[o] / acc;
}

// Kernel 2: Kv[b,p] = sum_t K[b,p,t] * v[b,t];  u = pred / Kv   (fused)
// One warp per (b,p) row; float4 loads; shuffle reduction.
__global__ void k_kv(const float* __restrict__ pred) {
    const int gw   = (blockIdx.x * blockDim.x + threadIdx.x) >> 5;
    const int lane = threadIdx.x & 31;
    const int b = gw >> 10;
    const int p = gw & 1023;

    const float4* __restrict__ Kr = (const float4*)(g_K + ((size_t)b * PP + p) * TT);
    const float4* __restrict__ vr = (const float4*)(g_v + b * TT);

    float acc = 0.f;
#pragma unroll
    for (int i = 0; i < 8; i++) {
        const float4 k4 = Kr[lane + 32 * i];
        const float4 v4 = vr[lane + 32 * i];
        acc += k4.x * v4.x + k4.y * v4.y + k4.z * v4.z + k4.w * v4.w;
    }
#pragma unroll
    for (int o = 16; o; o >>= 1)
        acc += __shfl_xor_sync(0xFFFFFFFFu, acc, o);
    if (lane == 0) {
        const int o = b * PP + p;
        g_u[o] = pred[o] / acc;
    }
}

// Kernel 3: P[b,p,t] = u[b,p] * K[b,p,t] * v[b,t]  (float4).
// One block covers exactly one (b,p) row of 1024 t-values.
__global__ void k_final(float* __restrict__ out) {
    const size_t i4 = (size_t)blockIdx.x * 256 + threadIdx.x;  // float4 index
    const size_t e  = i4 << 2;                                  // element index
    const int row = (int)(e >> 10);          // b*1024 + p
    const int b   = row >> 10;
    const int t4  = (int)(i4 & 255);         // float4 index within t-row

    const float u  = g_u[row];
    const float4 k = ((const float4*)g_K)[i4];
    const float4 v = ((const float4*)(g_v + b * TT))[t4];

    float4 r;
    r.x = u * k.x * v.x;
    r.y = u * k.y * v.y;
    r.z = u * k.z * v.z;
    r.w = u * k.w * v.w;
    ((float4*)out)[i4] = r;
}

extern "C" void kernel_launch(void* const* d_in, const int* in_sizes, int n_in,
                              void* d_out, int out_size) {
    const float* pred = (const float*)d_in[0];   // hist_pred (B,P)
    const float* tgt  = (const float*)d_in[1];   // hist_tgt  (B,T)
    const float* C    = (const float*)d_in[2];   // cost_matrix (B,P,T)
    const float* reg  = (const float*)d_in[3];   // scalar
    float* out = (float*)d_out;

    const int n4 = (BB * PP * TT) / 4;           // 16,777,216 float4s

    k_exp<<<n4 / 256, 256>>>(C, reg);

    for (int it = 0; it < 50; it++) {
        k_ktu<<<dim3(TT / 256, BB), 256>>>(tgt);
        k_kv<<<(BB * PP * 32) / 256, 256>>>(pred);
    }
    // final v, then P
    k_ktu<<<dim3(TT / 256, BB), 256>>>(tgt);
    k_final<<<n4 / 256, 256>>>(out);
}

// round 2
// speedup vs baseline: 1.0751x; 1.0751x over previous
#include <cuda_runtime.h>
#include <cuda_fp16.h>

#define BB 64
#define PP 1024
#define TT 1024

// fp16 Gibbs kernel: 134 MB, (almost) L2-resident on GB300 (126 MB L2).
__device__ __align__(16) __half g_Kh[(size_t)BB * PP * TT];
__device__ __align__(16) float  g_u[BB * PP];
__device__ __align__(16) float  g_v[BB * TT];

// Kernel 0: K = exp(-C/reg) -> fp16 (8 elems/thread), init u = 1.
__global__ void k_exp(const float* __restrict__ C, const float* __restrict__ reg) {
    const size_t i8 = (size_t)blockIdx.x * 256 + threadIdx.x;   // 8-element index
    const float ninv = -1.0f / reg[0];
    const float4* __restrict__ C4 = (const float4*)C;
    const float4 a = C4[2 * i8];
    const float4 c = C4[2 * i8 + 1];
    const __half2 h0 = __floats2half2_rn(__expf(a.x * ninv), __expf(a.y * ninv));
    const __half2 h1 = __floats2half2_rn(__expf(a.z * ninv), __expf(a.w * ninv));
    const __half2 h2 = __floats2half2_rn(__expf(c.x * ninv), __expf(c.y * ninv));
    const __half2 h3 = __floats2half2_rn(__expf(c.z * ninv), __expf(c.w * ninv));
    uint4 pack;
    __half2* ph = reinterpret_cast<__half2*>(&pack);
    ph[0] = h0; ph[1] = h1; ph[2] = h2; ph[3] = h3;
    ((uint4*)g_Kh)[i8] = pack;

    if (i8 < (BB * PP) / 4) {
        ((float4*)g_u)[i8] = make_float4(1.f, 1.f, 1.f, 1.f);
    }
}

// Kernel 1: Ktu[b,t] = sum_p K[b,p,t]*u[b,p]; v = tgt/Ktu.
// Block = 128 threads; each thread owns one half2 (2 adjacent t).
// Grid = (TT/256, BB) = 256 blocks. Unroll-8 over step-2 p -> 16 loads in flight.
__global__ void k_ktu(const float* __restrict__ tgt) {
    __shared__ float us[PP];
    const int b  = blockIdx.y;
    const int t2 = blockIdx.x * 128 + threadIdx.x;      // half2 index within T/2
    for (int p = threadIdx.x; p < PP; p += 128)
        us[p] = g_u[b * PP + p];
    __syncthreads();

    const __half2* __restrict__ Kb =
        (const __half2*)(g_Kh + (size_t)b * PP * TT) + t2;

    float2 acc0 = make_float2(0.f, 0.f);
    float2 acc1 = make_float2(0.f, 0.f);
#pragma unroll 8
    for (int p = 0; p < PP; p += 2) {
        const __half2 k0 = Kb[(size_t)(p + 0) * (TT / 2)];
        const __half2 k1 = Kb[(size_t)(p + 1) * (TT / 2)];
        const float2 f0 = __half22float2(k0);
        const float2 f1 = __half22float2(k1);
        const float u0 = us[p + 0], u1 = us[p + 1];
        acc0.x += f0.x * u0;  acc0.y += f0.y * u0;
        acc1.x += f1.x * u1;  acc1.y += f1.y * u1;
    }
    const float rx = acc0.x + acc1.x;
    const float ry = acc0.y + acc1.y;
    const int o = b * TT + 2 * t2;
    g_v[o + 0] = tgt[o + 0] / rx;
    g_v[o + 1] = tgt[o + 1] / ry;
}

// Kernel 2: Kv[b,p] = sum_t K[b,p,t]*v[b,t]; u = pred/Kv.
// Block = 256 threads (8 warps), one warp per p-row, all rows share b.
// v staged in shared; LDS.64 float2 reads are conflict-free; 16 half2 loads in flight.
__global__ void k_kv(const float* __restrict__ pred) {
    __shared__ float vs[TT];
    const int b = blockIdx.y;
    for (int t = threadIdx.x; t < TT; t += 256)
        vs[t] = g_v[b * TT + t];
    __syncthreads();

    const int wid  = threadIdx.x >> 5;
    const int lane = threadIdx.x & 31;
    const int p = blockIdx.x * 8 + wid;

    const __half2* __restrict__ Kr =
        (const __half2*)(g_Kh + ((size_t)b * PP + p) * TT);
    const float2* __restrict__ vs2 = (const float2*)vs;

    float2 acc = make_float2(0.f, 0.f);
#pragma unroll
    for (int i = 0; i < 16; i++) {
        const __half2 k2 = Kr[lane + 32 * i];
        const float2  v2 = vs2[lane + 32 * i];
        const float2  f  = __half22float2(k2);
        acc.x += f.x * v2.x;
        acc.y += f.y * v2.y;
    }
    float a = acc.x + acc.y;
#pragma unroll
    for (int o = 16; o; o >>= 1)
        a += __shfl_xor_sync(0xFFFFFFFFu, a, o);
    if (lane == 0) {
        const int o = b * PP + p;
        g_u[o] = pred[o] / a;
    }
}

// Kernel 3: P = u * exp(-C/reg) * v, recomputed in fp32 from C so the output
// never touches fp16 K. float4, 4 elems/thread.
__global__ void k_final(const float* __restrict__ C, const float* __restrict__ reg,
                        float* __restrict__ out) {
    const size_t i4 = (size_t)blockIdx.x * 256 + threadIdx.x;  // float4 index
    const float ninv = -1.0f / reg[0];
    const int row = (int)((i4 * 4) >> 10);     // b*1024 + p
    const int b   = row >> 10;
    const int t4  = (int)(i4 & 255);

    const float  u = g_u[row];
    const float4 c = ((const float4*)C)[i4];
    const float4 v = ((const float4*)(g_v + b * TT))[t4];

    float4 r;
    r.x = u * __expf(c.x * ninv) * v.x;
    r.y = u * __expf(c.y * ninv) * v.y;
    r.z = u * __expf(c.z * ninv) * v.z;
    r.w = u * __expf(c.w * ninv) * v.w;
    ((float4*)out)[i4] = r;
}

extern "C" void kernel_launch(void* const* d_in, const int* in_sizes, int n_in,
                              void* d_out, int out_size) {
    const float* pred = (const float*)d_in[0];   // hist_pred (B,P)
    const float* tgt  = (const float*)d_in[1];   // hist_tgt  (B,T)
    const float* C    = (const float*)d_in[2];   // cost_matrix (B,P,T)
    const float* reg  = (const float*)d_in[3];   // scalar
    float* out = (float*)d_out;

    const int n8 = (BB * PP * TT) / 8;   // 8,388,608 8-elem groups
    const int n4 = (BB * PP * TT) / 4;   // 16,777,216 float4s

    k_exp<<<n8 / 256, 256>>>(C, reg);

    for (int it = 0; it < 50; it++) {
        k_ktu<<<dim3(TT / 256, BB), 128>>>(tgt);
        k_kv<<<dim3(PP / 8, BB), 256>>>(pred);
    }
    k_ktu<<<dim3(TT / 256, BB), 128>>>(tgt);      // final v
    k_final<<<n4 / 256, 256>>>(C, reg, out);
}

// round 3
// speedup vs baseline: 1.7599x; 1.6369x over previous
#include <cuda_runtime.h>
#include <cuda_fp16.h>

#define BB 64
#define PP 1024
#define TT 1024
#define NITER 50

// fp16 Gibbs kernel, layout [b][p][t], t contiguous. 134 MB.
__device__ __align__(16) __half g_Kh[(size_t)BB * PP * TT];
__device__ __align__(16) float  g_u[BB * PP];
__device__ __align__(16) float  g_v[BB * TT];

// Kernel 0: K = exp(-C/reg) -> fp16, 8 elems/thread.
__global__ void k_exp(const float* __restrict__ C, const float* __restrict__ reg) {
    const size_t i8 = (size_t)blockIdx.x * 256 + threadIdx.x;
    const float ninv = -1.0f / reg[0];
    const float4* __restrict__ C4 = (const float4*)C;
    const float4 a = C4[2 * i8];
    const float4 c = C4[2 * i8 + 1];
    uint4 pack;
    __half2* ph = reinterpret_cast<__half2*>(&pack);
    ph[0] = __floats2half2_rn(__expf(a.x * ninv), __expf(a.y * ninv));
    ph[1] = __floats2half2_rn(__expf(a.z * ninv), __expf(a.w * ninv));
    ph[2] = __floats2half2_rn(__expf(c.x * ninv), __expf(c.y * ninv));
    ph[3] = __floats2half2_rn(__expf(c.z * ninv), __expf(c.w * ninv));
    ((uint4*)g_Kh)[i8] = pack;
}

// Persistent Sinkhorn: one block per batch, 1024 threads, all 50 iterations
// + final v in ONE launch. K slice per block = 2 MB (L2-resident reuse).
__global__ void __launch_bounds__(1024, 1)
k_sinkhorn(const float* __restrict__ pred, const float* __restrict__ tgt) {
    __shared__ float u_s[PP];
    __shared__ float v_s[TT];
    __shared__ float pred_s[PP];
    __shared__ float tgt_s[TT];
    __shared__ float buf[8 * TT];            // 32 KB partial-sum buffer

    const int b   = blockIdx.x;
    const int tid = threadIdx.x;

    pred_s[tid] = pred[b * PP + tid];
    tgt_s[tid]  = tgt[b * TT + tid];
    u_s[tid]    = 1.0f;
    __syncthreads();

    const __half* __restrict__ Kb = g_Kh + (size_t)b * PP * TT;
    const int sub  = tid >> 7;               // 0..7  : p-split group
    const int tx   = tid & 127;              // 0..127: t-tile owner (8 t each)
    const int wid  = tid >> 5;               // 0..31
    const int lane = tid & 31;

    for (int iter = 0; iter <= NITER; iter++) {
        // ---- pass 1: Ktu[t] = sum_p K[p][t] * u[p]; v = tgt / Ktu ----
        // thread owns t in [8*tx, 8*tx+8), reduces p in [128*sub, 128*sub+128)
        float acc[8];
#pragma unroll
        for (int j = 0; j < 8; j++) acc[j] = 0.0f;

        const uint4* __restrict__ Kr4 = (const uint4*)Kb + tx;  // row stride 128 uint4
        const int p0 = sub * 128;
#pragma unroll 4
        for (int pp = 0; pp < 128; pp++) {
            const int p = p0 + pp;
            const uint4 kk = Kr4[(size_t)p * (TT / 8)];
            const float up = u_s[p];
            const __half2* h = (const __half2*)&kk;
            const float2 f0 = __half22float2(h[0]);
            const float2 f1 = __half22float2(h[1]);
            const float2 f2 = __half22float2(h[2]);
            const float2 f3 = __half22float2(h[3]);
            acc[0] += f0.x * up;  acc[1] += f0.y * up;
            acc[2] += f1.x * up;  acc[3] += f1.y * up;
            acc[4] += f2.x * up;  acc[5] += f2.y * up;
            acc[6] += f3.x * up;  acc[7] += f3.y * up;
        }
#pragma unroll
        for (int j = 0; j < 8; j++)
            buf[sub * TT + 8 * tx + j] = acc[j];
        __syncthreads();

        float s = 0.0f;
#pragma unroll
        for (int sb = 0; sb < 8; sb++)
            s += buf[sb * TT + tid];
        v_s[tid] = tgt_s[tid] / s;
        __syncthreads();

        if (iter == NITER) break;             // 51st Ktu gives final v

        // ---- pass 2: Kv[p] = sum_t K[p][t] * v[t]; u = pred / Kv ----
        // warp handles 32 consecutive p rows; uint4 K loads, float4 v from smem
        const float4* __restrict__ vs4 = (const float4*)v_s;
        for (int r = 0; r < 32; r++) {
            const int p = wid * 32 + r;
            const uint4* __restrict__ Kp = (const uint4*)(Kb + (size_t)p * TT);
            float a = 0.0f;
#pragma unroll
            for (int i = 0; i < 4; i++) {
                const uint4 kk = Kp[lane + 32 * i];
                const float4 va = vs4[2 * (lane + 32 * i) + 0];
                const float4 vb = vs4[2 * (lane + 32 * i) + 1];
                const __half2* h = (const __half2*)&kk;
                const float2 f0 = __half22float2(h[0]);
                const float2 f1 = __half22float2(h[1]);
                const float2 f2 = __half22float2(h[2]);
                const float2 f3 = __half22float2(h[3]);
                a += f0.x * va.x + f0.y * va.y + f1.x * va.z + f1.y * va.w
                   + f2.x * vb.x + f2.y * vb.y + f3.x * vb.z + f3.y * vb.w;
            }
#pragma unroll
            for (int o = 16; o; o >>= 1)
                a += __shfl_xor_sync(0xFFFFFFFFu, a, o);
            if (lane == 0)
                u_s[p] = pred_s[p] / a;
        }
        __syncthreads();
    }

    g_u[b * PP + tid] = u_s[tid];
    g_v[b * TT + tid] = v_s[tid];
}

// Final: P = u * exp(-C/reg) * v in fp32 (output never touches fp16 K).
__global__ void k_final(const float* __restrict__ C, const float* __restrict__ reg,
                        float* __restrict__ out) {
    const size_t i4 = (size_t)blockIdx.x * 256 + threadIdx.x;
    const float ninv = -1.0f / reg[0];
    const int row = (int)((i4 * 4) >> 10);    // b*1024 + p
    const int b   = row >> 10;
    const int t4  = (int)(i4 & 255);

    const float  u = g_u[row];
    const float4 c = ((const float4*)C)[i4];
    const float4 v = ((const float4*)(g_v + b * TT))[t4];

    float4 r;
    r.x = u * __expf(c.x * ninv) * v.x;
    r.y = u * __expf(c.y * ninv) * v.y;
    r.z = u * __expf(c.z * ninv) * v.z;
    r.w = u * __expf(c.w * ninv) * v.w;
    ((float4*)out)[i4] = r;
}

extern "C" void kernel_launch(void* const* d_in, const int* in_sizes, int n_in,
                              void* d_out, int out_size) {
    const float* pred = (const float*)d_in[0];   // hist_pred (B,P)
    const float* tgt  = (const float*)d_in[1];   // hist_tgt  (B,T)
    const float* C    = (const float*)d_in[2];   // cost_matrix (B,P,T)
    const float* reg  = (const float*)d_in[3];   // scalar
    float* out = (float*)d_out;

    const int n8 = (BB * PP * TT) / 8;
    const int n4 = (BB * PP * TT) / 4;

    k_exp<<<n8 / 256, 256>>>(C, reg);
    k_sinkhorn<<<BB, 1024>>>(pred, tgt);
    k_final<<<n4 / 256, 256>>>(C, reg, out);
}

// round 5
// speedup vs baseline: 3.2325x; 1.8368x over previous
#include <cuda_runtime.h>
#include <cuda_fp16.h>
#include <cstdint>

#define BB 64
#define PP 1024
#define TT 1024
#define NITER 50
#define HALFP 512      // p-rows per cluster block

// fp16 Gibbs kernel, layout [b][p][t], t contiguous. 134 MB.
__device__ __align__(16) __half g_Kh[(size_t)BB * PP * TT];
__device__ __align__(16) float  g_u[BB * PP];
__device__ __align__(16) float  g_v[BB * TT];

// Kernel 0: K = exp(-C/reg) -> fp16, 8 elems/thread.
__global__ void k_exp(const float* __restrict__ C, const float* __restrict__ reg) {
    const size_t i8 = (size_t)blockIdx.x * 256 + threadIdx.x;
    const float ninv = -1.0f / reg[0];
    const float4* __restrict__ C4 = (const float4*)C;
    const float4 a = C4[2 * i8];
    const float4 c = C4[2 * i8 + 1];
    uint4 pack;
    __half2* ph = reinterpret_cast<__half2*>(&pack);
    ph[0] = __floats2half2_rn(__expf(a.x * ninv), __expf(a.y * ninv));
    ph[1] = __floats2half2_rn(__expf(a.z * ninv), __expf(a.w * ninv));
    ph[2] = __floats2half2_rn(__expf(c.x * ninv), __expf(c.y * ninv));
    ph[3] = __floats2half2_rn(__expf(c.z * ninv), __expf(c.w * ninv));
    ((uint4*)g_Kh)[i8] = pack;
}

// Persistent Sinkhorn: cluster of 2 CTAs per batch (128 CTAs total).
// Each CTA owns 512 p-rows (1 MB of K). Pass-1 partials exchanged via DSMEM.
__global__ void __launch_bounds__(1024, 1) __cluster_dims__(2, 1, 1)
k_sinkhorn(const float* __restrict__ pred, const float* __restrict__ tgt) {
    __shared__ float u_s[HALFP];           //  2 KB  (own p-half)
    __shared__ float v_s[TT];              //  4 KB
    __shared__ float buf[8 * TT];          // 32 KB  partial-sum tree
    __shared__ float part_peer[2][TT];     //  8 KB  peer partials, dbl-buffered

    const int tid = threadIdx.x;
    const int b   = blockIdx.x >> 1;
    const int r   = blockIdx.x & 1;        // cluster rank
    const int peer = r ^ 1;

    if (tid < HALFP) u_s[tid] = 1.0f;
    __syncthreads();

    const __half* __restrict__ Kb = g_Kh + ((size_t)b * PP + r * HALFP) * TT;
    const int sub  = tid >> 7;             // 0..7  : p-subgroup (64 rows each)
    const int tx   = tid & 127;            // 0..127: owns 8 t-values
    const int wid  = tid >> 5;             // 0..31
    const int lane = tid & 31;
    const float tgt_t = tgt[b * TT + tid];

    for (int iter = 0; iter <= NITER; iter++) {
        // ---- pass 1: partial Ktu over own p-half ----
        float acc[8];
#pragma unroll
        for (int j = 0; j < 8; j++) acc[j] = 0.0f;

        const uint4* __restrict__ Kr4 = (const uint4*)Kb + tx;  // row = 128 uint4
        const int p0 = sub * 64;
#pragma unroll 4
        for (int pp = 0; pp < 64; pp++) {
            const int p = p0 + pp;
            const uint4 kk = Kr4[(size_t)p * (TT / 8)];
            const float up = u_s[p];
            const __half2* h = (const __half2*)&kk;
            const float2 f0 = __half22float2(h[0]);
            const float2 f1 = __half22float2(h[1]);
            const float2 f2 = __half22float2(h[2]);
            const float2 f3 = __half22float2(h[3]);
            acc[0] += f0.x * up;  acc[1] += f0.y * up;
            acc[2] += f1.x * up;  acc[3] += f1.y * up;
            acc[4] += f2.x * up;  acc[5] += f2.y * up;
            acc[6] += f3.x * up;  acc[7] += f3.y * up;
        }
#pragma unroll
        for (int j = 0; j < 8; j++)
            buf[sub * TT + 8 * tx + j] = acc[j];
        __syncthreads();

        float s = 0.0f;
#pragma unroll
        for (int sb = 0; sb < 8; sb++)
            s += buf[sb * TT + tid];

        // exchange partials with peer CTA (double-buffered on iter parity)
        const int par = iter & 1;
        {
            unsigned int local = (unsigned int)__cvta_generic_to_shared(&part_peer[par][tid]);
            unsigned int remote;
            asm volatile("mapa.shared::cluster.u32 %0, %1, %2;"
                         : "=r"(remote) : "r"(local), "r"(peer));
            asm volatile("st.shared::cluster.f32 [%0], %1;"
                         :: "r"(remote), "f"(s) : "memory");
        }
        asm volatile("barrier.cluster.arrive.aligned;" ::: "memory");
        asm volatile("barrier.cluster.wait.aligned;" ::: "memory");

        v_s[tid] = tgt_t / (s + part_peer[par][tid]);
        __syncthreads();

        if (iter == NITER) break;          // 51st pass-1 yields final v

        // ---- pass 2: Kv over own p-half; u = pred/Kv ----
        const float4* __restrict__ vs4 = (const float4*)v_s;
        for (int rr = 0; rr < 16; rr++) {
            const int p = wid * 16 + rr;
            const uint4* __restrict__ Kp = (const uint4*)(Kb + (size_t)p * TT);
            float a = 0.0f;
#pragma unroll
            for (int i = 0; i < 4; i++) {
                const uint4 kk = Kp[lane + 32 * i];
                const float4 va = vs4[2 * (lane + 32 * i) + 0];
                const float4 vb = vs4[2 * (lane + 32 * i) + 1];
                const __half2* h = (const __half2*)&kk;
                const float2 f0 = __half22float2(h[0]);
                const float2 f1 = __half22float2(h[1]);
                const float2 f2 = __half22float2(h[2]);
                const float2 f3 = __half22float2(h[3]);
                a += f0.x * va.x + f0.y * va.y + f1.x * va.z + f1.y * va.w
                   + f2.x * vb.x + f2.y * vb.y + f3.x * vb.z + f3.y * vb.w;
            }
#pragma unroll
            for (int o = 16; o; o >>= 1)
                a += __shfl_xor_sync(0xFFFFFFFFu, a, o);
            if (lane == 0)
                u_s[p] = pred[b * PP + r * HALFP + p] / a;
        }
        __syncthreads();
    }

    if (tid < HALFP)
        g_u[b * PP + r * HALFP + tid] = u_s[tid];
    if (r == 0)
        g_v[b * TT + tid] = v_s[tid];
}

// Final: P = u * Kh * v  (fp16 K read back; 8 elems/thread).
__global__ void k_final(float* __restrict__ out) {
    const size_t i8 = (size_t)blockIdx.x * 256 + threadIdx.x;  // uint4 index
    const int row = (int)(i8 >> 7);          // b*1024 + p
    const int b   = row >> 10;
    const int t8  = (int)(i8 & 127);         // 8-elem group within t-row

    const float u = g_u[row];
    const uint4 kk = ((const uint4*)g_Kh)[i8];
    const float4* vr = (const float4*)(g_v + b * TT) + 2 * t8;
    const float4 va = vr[0];
    const float4 vb = vr[1];

    const __half2* h = (const __half2*)&kk;
    const float2 f0 = __half22float2(h[0]);
    const float2 f1 = __half22float2(h[1]);
    const float2 f2 = __half22float2(h[2]);
    const float2 f3 = __half22float2(h[3]);

    float4 o0, o1;
    o0.x = u * f0.x * va.x;  o0.y = u * f0.y * va.y;
    o0.z = u * f1.x * va.z;  o0.w = u * f1.y * va.w;
    o1.x = u * f2.x * vb.x;  o1.y = u * f2.y * vb.y;
    o1.z = u * f3.x * vb.z;  o1.w = u * f3.y * vb.w;

    float4* out4 = (float4*)out;
    out4[2 * i8 + 0] = o0;
    out4[2 * i8 + 1] = o1;
}

extern "C" void kernel_launch(void* const* d_in, const int* in_sizes, int n_in,
                              void* d_out, int out_size) {
    const float* pred = (const float*)d_in[0];   // hist_pred (B,P)
    const float* tgt  = (const float*)d_in[1];   // hist_tgt  (B,T)
    const float* C    = (const float*)d_in[2];   // cost_matrix (B,P,T)
    const float* reg  = (const float*)d_in[3];   // scalar
    float* out = (float*)d_out;

    const int n8 = (BB * PP * TT) / 8;

    k_exp<<<n8 / 256, 256>>>(C, reg);
    k_sinkhorn<<<2 * BB, 1024>>>(pred, tgt);
    k_final<<<n8 / 256, 256>>>(out);
}

// round 6
// speedup vs baseline: 3.9876x; 1.2336x over previous
#include <cuda_runtime.h>
#include <cuda_fp16.h>
#include <cstdint>

#define BB 64
#define PP 1024
#define TT 1024
#define NITER 50
#define HALFP 512      // p-rows per cluster CTA

// fp16 Gibbs kernel, layout [b][p][t], t contiguous. 134 MB.
__device__ __align__(16) __half g_Kh[(size_t)BB * PP * TT];
__device__ __align__(16) float  g_u[BB * PP];
__device__ __align__(16) float  g_v[BB * TT];

// K = exp(-C/reg) -> fp16, 8 elems/thread.
__global__ void k_exp(const float* __restrict__ C, const float* __restrict__ reg) {
    const size_t i8 = (size_t)blockIdx.x * 256 + threadIdx.x;
    const float ninv = -1.0f / reg[0];
    const float4* __restrict__ C4 = (const float4*)C;
    const float4 a = C4[2 * i8];
    const float4 c = C4[2 * i8 + 1];
    uint4 pack;
    __half2* ph = reinterpret_cast<__half2*>(&pack);
    ph[0] = __floats2half2_rn(__expf(a.x * ninv), __expf(a.y * ninv));
    ph[1] = __floats2half2_rn(__expf(a.z * ninv), __expf(a.w * ninv));
    ph[2] = __floats2half2_rn(__expf(c.x * ninv), __expf(c.y * ninv));
    ph[3] = __floats2half2_rn(__expf(c.z * ninv), __expf(c.w * ninv));
    ((uint4*)g_Kh)[i8] = pack;
}

// Persistent fused Sinkhorn: cluster of 2 CTAs per batch (128 CTAs).
// ONE pass over K per iteration: while streaming row p, compute
// u_p = pred_p/(K_p·v) and accumulate u_p*K_p into next Ktu.
__global__ void __launch_bounds__(512, 1) __cluster_dims__(2, 1, 1)
k_sinkhorn(const float* __restrict__ pred, const float* __restrict__ tgt) {
    __shared__ float v_s[TT];             //  4 KB
    __shared__ float u_s[HALFP];          //  2 KB
    __shared__ float buf[8][TT];          // 32 KB warp-combine tree
    __shared__ float part_peer[2][TT];    //  8 KB DSMEM partials, parity dbl-buf
    __shared__ float pred_s[HALFP];       //  2 KB

    const int tid  = threadIdx.x;         // 0..511
    const int b    = blockIdx.x >> 1;
    const int r    = blockIdx.x & 1;
    const int peer = r ^ 1;
    const int wid  = tid >> 5;            // 0..15
    const int lane = tid & 31;

    pred_s[tid] = pred[b * PP + r * HALFP + tid];
    const float tgt_a = tgt[b * TT + tid];
    const float tgt_b = tgt[b * TT + tid + 512];
    __syncthreads();

    const uint4* __restrict__ K4 =
        (const uint4*)(g_Kh + ((size_t)b * PP + (size_t)r * HALFP) * TT);
    const size_t row0 = (size_t)(wid * 32) * 128;   // uint4 index of warp's row 0

    for (int iter = 0; iter <= NITER; iter++) {
        // v in registers; lane's fixed t-positions: t = 8*(lane+32*i)+j
        float vreg[32];
        if (iter > 0) {
            const float4* __restrict__ vs4 = (const float4*)v_s;
#pragma unroll
            for (int i = 0; i < 4; i++) {
                const float4 va = vs4[2 * (lane + 32 * i) + 0];
                const float4 vb = vs4[2 * (lane + 32 * i) + 1];
                vreg[8*i+0]=va.x; vreg[8*i+1]=va.y; vreg[8*i+2]=va.z; vreg[8*i+3]=va.w;
                vreg[8*i+4]=vb.x; vreg[8*i+5]=vb.y; vreg[8*i+6]=vb.z; vreg[8*i+7]=vb.w;
            }
        }

        float acc[32];
#pragma unroll
        for (int j = 0; j < 32; j++) acc[j] = 0.0f;

        // prefetch row 0
        uint4 k4[4];
#pragma unroll
        for (int i = 0; i < 4; i++) k4[i] = K4[row0 + lane + 32 * i];

#pragma unroll 4
        for (int rr = 0; rr < 32; rr++) {
            uint4 kn[4];
            if (rr < 31) {                 // prefetch next row
                const size_t nrow = row0 + (size_t)(rr + 1) * 128;
#pragma unroll
                for (int i = 0; i < 4; i++) kn[i] = K4[nrow + lane + 32 * i];
            }

            const __half2* h = (const __half2*)k4;   // 16 half2
            if (iter == 0) {
                // u = 1: just accumulate K into Ktu partials
#pragma unroll
                for (int q = 0; q < 16; q++) {
                    const float2 f = __half22float2(h[q]);
                    acc[2*q+0] += f.x;
                    acc[2*q+1] += f.y;
                }
            } else {
                // dot(K_p, v)
                float a = 0.0f;
#pragma unroll
                for (int q = 0; q < 16; q++) {
                    const float2 f = __half22float2(h[q]);
                    a += f.x * vreg[2*q+0] + f.y * vreg[2*q+1];
                }
#pragma unroll
                for (int o = 16; o; o >>= 1)
                    a += __shfl_xor_sync(0xFFFFFFFFu, a, o);

                const int p = wid * 32 + rr;
                const float up = __fdividef(pred_s[p], a);
                if (iter == NITER && lane == 0) u_s[p] = up;

                // accumulate u_p * K_p into next Ktu (re-convert from k4)
#pragma unroll
                for (int q = 0; q < 16; q++) {
                    const float2 f = __half22float2(h[q]);
                    acc[2*q+0] += up * f.x;
                    acc[2*q+1] += up * f.y;
                }
            }
#pragma unroll
            for (int i = 0; i < 4; i++) k4[i] = kn[i];
        }

        // combine 16 warps -> buf[8][TT] (two rounds)
        if (wid < 8) {
            float4* __restrict__ dst = (float4*)&buf[wid][0];
#pragma unroll
            for (int i = 0; i < 4; i++) {
                const int idx = lane + 32 * i;
                dst[2*idx+0] = make_float4(acc[8*i+0], acc[8*i+1], acc[8*i+2], acc[8*i+3]);
                dst[2*idx+1] = make_float4(acc[8*i+4], acc[8*i+5], acc[8*i+6], acc[8*i+7]);
            }
        }
        __syncthreads();
        if (wid >= 8) {
            float4* __restrict__ dst = (float4*)&buf[wid - 8][0];
#pragma unroll
            for (int i = 0; i < 4; i++) {
                const int idx = lane + 32 * i;
                float4 x = dst[2*idx+0];
                x.x += acc[8*i+0]; x.y += acc[8*i+1]; x.z += acc[8*i+2]; x.w += acc[8*i+3];
                dst[2*idx+0] = x;
                float4 y = dst[2*idx+1];
                y.x += acc[8*i+4]; y.y += acc[8*i+5]; y.z += acc[8*i+6]; y.w += acc[8*i+7];
                dst[2*idx+1] = y;
            }
        }
        __syncthreads();

        float s0 = 0.0f, s1 = 0.0f;
#pragma unroll
        for (int k = 0; k < 8; k++) {
            s0 += buf[k][tid];
            s1 += buf[k][tid + 512];
        }

        // DSMEM exchange with peer CTA (parity double-buffer)
        const int par = iter & 1;
        {
            unsigned int l0 = (unsigned int)__cvta_generic_to_shared(&part_peer[par][tid]);
            unsigned int l1 = (unsigned int)__cvta_generic_to_shared(&part_peer[par][tid + 512]);
            unsigned int r0, r1;
            asm volatile("mapa.shared::cluster.u32 %0, %1, %2;" : "=r"(r0) : "r"(l0), "r"(peer));
            asm volatile("mapa.shared::cluster.u32 %0, %1, %2;" : "=r"(r1) : "r"(l1), "r"(peer));
            asm volatile("st.shared::cluster.f32 [%0], %1;" :: "r"(r0), "f"(s0) : "memory");
            asm volatile("st.shared::cluster.f32 [%0], %1;" :: "r"(r1), "f"(s1) : "memory");
        }
        asm volatile("barrier.cluster.arrive.aligned;" ::: "memory");
        asm volatile("barrier.cluster.wait.aligned;" ::: "memory");

        v_s[tid]       = tgt_a / (s0 + part_peer[par][tid]);
        v_s[tid + 512] = tgt_b / (s1 + part_peer[par][tid + 512]);
        __syncthreads();
    }

    g_u[b * PP + r * HALFP + tid] = u_s[tid];
    if (r == 0) {
        g_v[b * TT + tid]       = v_s[tid];
        g_v[b * TT + tid + 512] = v_s[tid + 512];
    }
}

// Final: P = u * Kh * v  (fp16 K; 8 elems/thread).
__global__ void k_final(float* __restrict__ out) {
    const size_t i8 = (size_t)blockIdx.x * 256 + threadIdx.x;  // uint4 index
    const int row = (int)(i8 >> 7);          // b*1024 + p
    const int b   = row >> 10;
    const int t8  = (int)(i8 & 127);

    const float u = g_u[row];
    const uint4 kk = ((const uint4*)g_Kh)[i8];
    const float4* vr = (const float4*)(g_v + b * TT) + 2 * t8;
    const float4 va = vr[0];
    const float4 vb = vr[1];

    const __half2* h = (const __half2*)&kk;
    const float2 f0 = __half22float2(h[0]);
    const float2 f1 = __half22float2(h[1]);
    const float2 f2 = __half22float2(h[2]);
    const float2 f3 = __half22float2(h[3]);

    float4 o0, o1;
    o0.x = u * f0.x * va.x;  o0.y = u * f0.y * va.y;
    o0.z = u * f1.x * va.z;  o0.w = u * f1.y * va.w;
    o1.x = u * f2.x * vb.x;  o1.y = u * f2.y * vb.y;
    o1.z = u * f3.x * vb.z;  o1.w = u * f3.y * vb.w;

    float4* out4 = (float4*)out;
    out4[2 * i8 + 0] = o0;
    out4[2 * i8 + 1] = o1;
}

extern "C" void kernel_launch(void* const* d_in, const int* in_sizes, int n_in,
                              void* d_out, int out_size) {
    const float* pred = (const float*)d_in[0];
    const float* tgt  = (const float*)d_in[1];
    const float* C    = (const float*)d_in[2];
    const float* reg  = (const float*)d_in[3];
    float* out = (float*)d_out;

    const int n8 = (BB * PP * TT) / 8;

    k_exp<<<n8 / 256, 256>>>(C, reg);
    k_sinkhorn<<<2 * BB, 512>>>(pred, tgt);
    k_final<<<n8 / 256, 256>>>(out);
}